// round 15
// baseline (speedup 1.0000x reference)
#include <cuda_runtime.h>

#define N_ 4
#define C_ 256
#define H_ 200
#define W_ 272
#define O_ 7
#define K_CH 8          // h-chunks
#define HCH 25          // H_ / K_CH

// Integral image, 16-group-blocked TRANSPOSED layout:
//   g_integ[(((n*H + h)*16 + g)*W + w)*16 + ci]  with g=c>>4, ci=c&15.
__device__ float g_integ[(size_t)N_ * H_ * W_ * C_];
// carry, same layout: [n][k][g][w][ci]
__device__ float g_carry[(size_t)N_ * K_CH * W_ * C_];

__device__ __forceinline__ float4 f4add(float4 a, float4 b) {
    return make_float4(a.x + b.x, a.y + b.y, a.z + b.z, a.w + b.w);
}
__device__ __forceinline__ float4 f4sub(float4 a, float4 b) {
    return make_float4(a.x - b.x, a.y - b.y, a.z - b.z, a.w - b.w);
}

// compact piece -> physical xch slot (rotation keyed on sgrp = p>>3;
// conflict-free for the stride-128B writer and the linear reader)
__device__ __forceinline__ int xphys(int p) {
    const int sgrp = p >> 3, off = p & 7;
    return 8 * sgrp + ((off + sgrp) & 7);
}

// --------------------------------------------------------------------------
// Fused H-scan + W-scan + transpose. Block: 96 threads (3 warps) owning the
// 8-channel half (tf) of c-group g; thread = 4 consecutive w (68 active).
// Software-pipelined loads; reg-trimmed + forced 6 blocks/SM.
// Grid: (32, 8, 4) = 1024 blocks.
// --------------------------------------------------------------------------
__global__ void __launch_bounds__(96, 6) fused_scan(const float* __restrict__ fm) {
    __shared__ float  wsum[8][3];        // [channel][warp]
    __shared__ float4 xch[2][544];       // double-buffered half-row stage

    const int ct = blockIdx.x;           // 8-channel team id, 0..31
    const int g  = ct >> 1;              // c-group of 16
    const int tf = ct & 1;               // which half of the group
    const int c0 = ct * 8;
    const int k  = blockIdx.y;
    const int n  = blockIdx.z;
    const int s    = threadIdx.x;        // 0..95, active < 68
    const int lane = s & 31;
    const int wiw  = s >> 5;             // warp, 0..2
    const bool active = (s < 68);

    // ---- loop-invariant addresses ----
    int st_idx[8];                       // staging: compact i = 8s + (2e+qq)
    #pragma unroll
    for (int q = 0; q < 8; ++q)
        st_idx[q] = 8 * s + ((q + s) & 7);

    int wo_src[6];                       // writeout smem slots (non-linear)
    #pragma unroll
    for (int t = 0; t < 6; ++t)
        wo_src[t] = xphys(s + 96 * t);
    // writeout dst is an arithmetic progression: dst(t) = dst0 + 192t
    const int dst0 = 4 * (s >> 1) + 2 * tf + (s & 1);

    float acc[8][4];
    #pragma unroll
    for (int j = 0; j < 8; ++j)
        #pragma unroll
        for (int e = 0; e < 4; ++e) acc[j][e] = 0.f;

    const float4* in0 = (const float4*)(fm + ((size_t)(n * C_ + c0) * H_
                          + (size_t)k * HCH) * W_) + (active ? s : 0);
    float4* gout0 = (float4*)g_integ
        + ((size_t)((n * H_ + k * HCH) * 16 + g)) * (W_ * 4);

    // prologue: load row 0
    float4 v[8];
    #pragma unroll
    for (int j = 0; j < 8; ++j)
        v[j] = in0[(size_t)j * (H_ * W_ / 4)];

    for (int lh = 0; lh < HCH; ++lh) {
        const int buf = lh & 1;

        float sc[8][4];
        #pragma unroll
        for (int j = 0; j < 8; ++j) {
            if (!active) v[j] = make_float4(0.f, 0.f, 0.f, 0.f);
            acc[j][0] += v[j].x;
            acc[j][1] += v[j].y;
            acc[j][2] += v[j].z;
            acc[j][3] += v[j].w;
            const float i0 = acc[j][0];
            const float i1 = i0 + acc[j][1];
            const float i2 = i1 + acc[j][2];
            const float i3 = i2 + acc[j][3];
            float x = i3;                          // warp inclusive scan on totals
            #pragma unroll
            for (int d = 1; d < 32; d <<= 1) {
                float y = __shfl_up_sync(0xffffffff, x, d);
                if (lane >= d) x += y;
            }
            const float excl = x - i3;
            sc[j][0] = i0 + excl;
            sc[j][1] = i1 + excl;
            sc[j][2] = i2 + excl;
            sc[j][3] = i3 + excl;
            if (lane == 31) wsum[j][wiw] = x;
        }
        __syncthreads();                           // wsum ready

        #pragma unroll
        for (int j = 0; j < 8; ++j) {
            float p = 0.f;
            #pragma unroll
            for (int t = 0; t < 2; ++t)
                if (t < wiw) p += wsum[j][t];
            #pragma unroll
            for (int e = 0; e < 4; ++e) sc[j][e] += p;
        }

        // stage: compact piece i = 8s + (2e+qq) holds channels 4qq..4qq+3
        // of w = 4s+e.
        if (active) {
            #pragma unroll
            for (int e = 0; e < 4; ++e) {
                #pragma unroll
                for (int qq = 0; qq < 2; ++qq)
                    xch[buf][st_idx[2 * e + qq]] =
                        make_float4(sc[4 * qq + 0][e], sc[4 * qq + 1][e],
                                    sc[4 * qq + 2][e], sc[4 * qq + 3][e]);
            }
        }

        // software pipeline: issue next row's loads now (sc regs are dead;
        // loads overlap the barrier + writeout below).
        if (lh + 1 < HCH) {
            #pragma unroll
            for (int j = 0; j < 8; ++j)
                v[j] = in0[(size_t)j * (H_ * W_ / 4) + (lh + 1) * (W_ / 4)];
        }
        __syncthreads();                           // xch[buf] ready

        // writeout: strided float4 pairs (2 on / 2 off) into the G16 row.
        float4* gout = gout0 + (size_t)lh * (64 * W_) + dst0;
        #pragma unroll
        for (int t = 0; t < 5; ++t)
            gout[192 * t] = xch[buf][wo_src[t]];
        if (s < 64)
            gout[192 * 5] = xch[buf][wo_src[5]];
    }
}

// --------------------------------------------------------------------------
// carry[n][k][g][w][ci]: exclusive prefix over chunks of each chunk's
// last row. Linear thread index, ci fastest -> coalesced.
// --------------------------------------------------------------------------
__global__ void chunk_carry() {
    const int total = N_ * 16 * W_ * 16;
    int idx = blockIdx.x * 256 + threadIdx.x;
    if (idx >= total) return;
    const int ci = idx & 15;
    const int w  = (idx >> 4) % W_;
    const int g  = ((idx >> 4) / W_) & 15;
    const int n  = idx / (16 * W_ * 16);

    float p = 0.f;
    #pragma unroll
    for (int k = 0; k < K_CH; ++k) {
        g_carry[((((size_t)(n * K_CH + k) * 16 + g) * W_ + w) << 4) + ci] = p;
        p += g_integ[((((size_t)(n * H_ + k * HCH + (HCH - 1)) * 16 + g) * W_ + w) << 4) + ci];
    }
}

// --------------------------------------------------------------------------
// Per-ROI gather. Grid (R, 2): block = (ROI r, phase ph) covering 128
// channels each (25KB smem staging -> 8 blocks/SM).
// Thread = (local quad lq = t&31, bin-group grp = t>>5).
// Global quad cq = ph*32+lq -> group g = cq>>2, sub = cq&3; channels = 4*cq.
// --------------------------------------------------------------------------
__global__ void roipool(const int* __restrict__ rois, float* __restrict__ out,
                        int img_off, int R) {
    extern __shared__ float stage[];       // 128 * 49 floats = 25088 B
    __shared__ int sb[4 * O_];             // hs[7] he[7] ws[7] we[7]
    const int r = blockIdx.x;
    if (r >= R) return;
    const int ph  = blockIdx.y;            // 0 or 1
    const int t   = threadIdx.x;
    const int lq  = t & 31;
    const int grp = t >> 5;                // 0..7

    const int n  = rois[r * 5 + 0];
    const int x1 = rois[r * 5 + 1];
    const int y1 = rois[r * 5 + 2];
    const int x2 = rois[r * 5 + 3];
    const int y2 = rois[r * 5 + 4];

    if (t < O_) {
        const int hin = y2 - y1 + 1;
        const int win = x2 - x1 + 1;
        sb[t]          = y1 + (t * hin) / O_;                   // hs
        sb[O_ + t]     = y1 + ((t + 1) * hin + O_ - 1) / O_;    // he
        sb[2 * O_ + t] = x1 + (t * win) / O_;                   // ws
        sb[3 * O_ + t] = x1 + ((t + 1) * win + O_ - 1) / O_;    // we
    }
    __syncthreads();

    if (img_off > 0 && t == 0 && ph == 0) out[r] = (float)n;   // img_idx

    const float4 z4 = make_float4(0.f, 0.f, 0.f, 0.f);

    const int cq  = ph * 32 + lq;
    const int gg  = cq >> 2;
    const int sub = cq & 3;

    // float4 bases; per-h (or per-k) stride = 16 groups * 4W = 64W float4
    const float4* ib = (const float4*)g_integ
        + (size_t)n * ((size_t)H_ * 64 * W_) + (size_t)gg * (4 * W_) + sub;
    const float4* cb = (const float4*)g_carry
        + (size_t)n * ((size_t)K_CH * 64 * W_) + (size_t)gg * (4 * W_) + sub;

    #pragma unroll
    for (int m = 0; m < 7; ++m) {
        const int b = grp + 8 * m;
        if (b < O_ * O_) {
            const int i = b / O_;
            const int j = b - i * O_;
            const int hiT = sb[i];
            const int hiB = sb[O_ + i];
            const int wL  = sb[2 * O_ + j] - 1;   // may be -1 (pad)
            const int wR  = sb[3 * O_ + j] - 1;
            const int kB  = (hiB - 1) / HCH;
            const int kT  = (hiT > 0) ? (hiT - 1) / HCH : 0;

            // chunk-local integral corners
            float4 BR = ib[(size_t)(hiB - 1) * (64 * W_) + 4 * wR];
            float4 TR = (hiT > 0) ? ib[(size_t)(hiT - 1) * (64 * W_) + 4 * wR] : z4;
            float4 BL = (wL >= 0) ? ib[(size_t)(hiB - 1) * (64 * W_) + 4 * wL] : z4;
            float4 TL = (hiT > 0 && wL >= 0)
                      ? ib[(size_t)(hiT - 1) * (64 * W_) + 4 * wL] : z4;
            float4 s = f4sub(f4sub(BR, TR), f4sub(BL, TL));

            // carry correction; cancels when both rows in one chunk
            const bool need_carry = (hiT > 0) ? (kB != kT) : (kB != 0);
            if (need_carry) {
                float4 cR = cb[(size_t)kB * (64 * W_) + 4 * wR];
                if (hiT > 0) cR = f4sub(cR, cb[(size_t)kT * (64 * W_) + 4 * wR]);
                float4 cL = z4;
                if (wL >= 0) {
                    cL = cb[(size_t)kB * (64 * W_) + 4 * wL];
                    if (hiT > 0) cL = f4sub(cL, cb[(size_t)kT * (64 * W_) + 4 * wL]);
                }
                s = f4add(s, f4sub(cR, cL));
            }

            const float inv = 1.f / ((float)(hiB - hiT) *
                                     (float)(sb[3 * O_ + j] - sb[2 * O_ + j]));
            const int base = (4 * lq) * (O_ * O_) + b;
            stage[base]                 = s.x * inv;
            stage[base + O_ * O_]       = s.y * inv;
            stage[base + 2 * (O_ * O_)] = s.z * inv;
            stage[base + 3 * (O_ * O_)] = s.w * inv;
        }
    }
    __syncthreads();

    // coalesced float4 writeout of this half (128 ch * 49 bins)
    float4* o4 = (float4*)(out + img_off + (size_t)r * (C_ * O_ * O_)
                           + (size_t)ph * (128 * O_ * O_));
    const float4* s4 = (const float4*)stage;
    const int n4 = 128 * O_ * O_ / 4;   // 1568
    for (int p = t; p < n4; p += 256) o4[p] = s4[p];
}

// --------------------------------------------------------------------------
extern "C" void kernel_launch(void* const* d_in, const int* in_sizes, int n_in,
                              void* d_out, int out_size) {
    const float* fm   = (const float*)d_in[0];
    const int*   rois = (const int*)d_in[1];
    const int R = in_sizes[1] / 5;

    int img_off = out_size - R * C_ * O_ * O_;
    if (img_off < 0) img_off = 0;

    const int smem_bytes = 128 * O_ * O_ * (int)sizeof(float);   // 25088
    cudaFuncSetAttribute(roipool, cudaFuncAttributeMaxDynamicSharedMemorySize,
                         smem_bytes);

    dim3 gF(32, K_CH, N_);
    fused_scan<<<gF, 96>>>(fm);

    const int tot = N_ * C_ * W_;
    chunk_carry<<<(tot + 255) / 256, 256>>>();

    dim3 gR(R, 2);
    roipool<<<gR, 256, smem_bytes>>>(rois, (float*)d_out, img_off, R);
}

// round 16
// speedup vs baseline: 1.4652x; 1.4652x over previous
#include <cuda_runtime.h>

#define N_ 4
#define C_ 256
#define H_ 200
#define W_ 272
#define O_ 7
#define K_CH 10         // h-chunks
#define HCH 20          // H_ / K_CH

// Integral image, 16-group-blocked TRANSPOSED layout:
//   g_integ[(((n*H + h)*16 + g)*W + w)*16 + ci]  with g=c>>4, ci=c&15.
__device__ float g_integ[(size_t)N_ * H_ * W_ * C_];
// carry, same layout: [n][k][g][w][ci]
__device__ float g_carry[(size_t)N_ * K_CH * W_ * C_];

__device__ __forceinline__ float4 f4add(float4 a, float4 b) {
    return make_float4(a.x + b.x, a.y + b.y, a.z + b.z, a.w + b.w);
}
__device__ __forceinline__ float4 f4sub(float4 a, float4 b) {
    return make_float4(a.x - b.x, a.y - b.y, a.z - b.z, a.w - b.w);
}

// compact piece -> physical xch slot (rotation keyed on sgrp = p>>3;
// conflict-free for the stride-128B writer and the linear reader)
__device__ __forceinline__ int xphys(int p) {
    const int sgrp = p >> 3, off = p & 7;
    return 8 * sgrp + ((off + sgrp) & 7);
}

// --------------------------------------------------------------------------
// Fused H-scan + W-scan + transpose (EXACT R14 structure: 128 regs is the
// pipeline's working set — do NOT cap blocks; caps cause local-mem spills).
// Block: 96 threads (3 warps) owning the 8-channel half (tf) of c-group g;
// thread = 4 consecutive w (68 active). Software-pipelined loads.
// Grid: (32, 10, 4) = 1280 blocks, ~5-7 blocks/SM.
// --------------------------------------------------------------------------
__global__ void __launch_bounds__(96) fused_scan(const float* __restrict__ fm) {
    __shared__ float  wsum[8][3];        // [channel][warp]
    __shared__ float4 xch[2][544];       // double-buffered half-row stage

    const int ct = blockIdx.x;           // 8-channel team id, 0..31
    const int g  = ct >> 1;              // c-group of 16
    const int tf = ct & 1;               // which half of the group
    const int c0 = ct * 8;
    const int k  = blockIdx.y;
    const int n  = blockIdx.z;
    const int s    = threadIdx.x;        // 0..95, active < 68
    const int lane = s & 31;
    const int wiw  = s >> 5;             // warp, 0..2
    const bool active = (s < 68);

    // ---- loop-invariant addresses ----
    int st_idx[8];                       // staging: compact i = 8s + (2e+qq)
    #pragma unroll
    for (int q = 0; q < 8; ++q)
        st_idx[q] = 8 * s + ((q + s) & 7);

    int wo_src[6], wo_dst[6];            // writeout: compact p = s + 96t
    #pragma unroll
    for (int t = 0; t < 6; ++t) {
        const int p = s + 96 * t;
        wo_src[t] = xphys(p);
        wo_dst[t] = 4 * (p >> 1) + 2 * tf + (p & 1);
    }
    const bool has6 = (s < 544 - 5 * 96);   // s < 64

    float acc[8][4];
    #pragma unroll
    for (int j = 0; j < 8; ++j)
        #pragma unroll
        for (int e = 0; e < 4; ++e) acc[j][e] = 0.f;

    const float4* in0 = (const float4*)(fm + ((size_t)(n * C_ + c0) * H_
                          + (size_t)k * HCH) * W_) + (active ? s : 0);
    float4* gout0 = (float4*)g_integ
        + ((size_t)((n * H_ + k * HCH) * 16 + g)) * (W_ * 4);

    // prologue: load row 0
    float4 v[8];
    #pragma unroll
    for (int j = 0; j < 8; ++j)
        v[j] = in0[(size_t)j * (H_ * W_ / 4)];

    for (int lh = 0; lh < HCH; ++lh) {
        const int buf = lh & 1;

        float sc[8][4];
        #pragma unroll
        for (int j = 0; j < 8; ++j) {
            if (!active) v[j] = make_float4(0.f, 0.f, 0.f, 0.f);
            acc[j][0] += v[j].x;
            acc[j][1] += v[j].y;
            acc[j][2] += v[j].z;
            acc[j][3] += v[j].w;
            const float i0 = acc[j][0];
            const float i1 = i0 + acc[j][1];
            const float i2 = i1 + acc[j][2];
            const float i3 = i2 + acc[j][3];
            float x = i3;                          // warp inclusive scan on totals
            #pragma unroll
            for (int d = 1; d < 32; d <<= 1) {
                float y = __shfl_up_sync(0xffffffff, x, d);
                if (lane >= d) x += y;
            }
            const float excl = x - i3;
            sc[j][0] = i0 + excl;
            sc[j][1] = i1 + excl;
            sc[j][2] = i2 + excl;
            sc[j][3] = i3 + excl;
            if (lane == 31) wsum[j][wiw] = x;
        }
        __syncthreads();                           // wsum ready

        #pragma unroll
        for (int j = 0; j < 8; ++j) {
            float p = 0.f;
            #pragma unroll
            for (int t = 0; t < 2; ++t)
                if (t < wiw) p += wsum[j][t];
            #pragma unroll
            for (int e = 0; e < 4; ++e) sc[j][e] += p;
        }

        // stage: compact piece i = 8s + (2e+qq) holds channels 4qq..4qq+3
        // of w = 4s+e.
        if (active) {
            #pragma unroll
            for (int e = 0; e < 4; ++e) {
                #pragma unroll
                for (int qq = 0; qq < 2; ++qq)
                    xch[buf][st_idx[2 * e + qq]] =
                        make_float4(sc[4 * qq + 0][e], sc[4 * qq + 1][e],
                                    sc[4 * qq + 2][e], sc[4 * qq + 3][e]);
            }
        }

        // software pipeline: issue next row's loads now (sc regs are dead;
        // loads overlap the barrier + writeout below).
        if (lh + 1 < HCH) {
            #pragma unroll
            for (int j = 0; j < 8; ++j)
                v[j] = in0[(size_t)j * (H_ * W_ / 4) + (lh + 1) * (W_ / 4)];
        }
        __syncthreads();                           // xch[buf] ready

        // writeout: strided float4 pairs (2 on / 2 off) into the G16 row.
        float4* gout = gout0 + (size_t)lh * (64 * W_);
        #pragma unroll
        for (int t = 0; t < 5; ++t)
            gout[wo_dst[t]] = xch[buf][wo_src[t]];
        if (has6)
            gout[wo_dst[5]] = xch[buf][wo_src[5]];
    }
}

// --------------------------------------------------------------------------
// carry[n][k][g][w][ci]: exclusive prefix over chunks of each chunk's
// last row. Linear thread index, ci fastest -> coalesced.
// --------------------------------------------------------------------------
__global__ void chunk_carry() {
    const int total = N_ * 16 * W_ * 16;
    int idx = blockIdx.x * 256 + threadIdx.x;
    if (idx >= total) return;
    const int ci = idx & 15;
    const int w  = (idx >> 4) % W_;
    const int g  = ((idx >> 4) / W_) & 15;
    const int n  = idx / (16 * W_ * 16);

    float p = 0.f;
    #pragma unroll
    for (int k = 0; k < K_CH; ++k) {
        g_carry[((((size_t)(n * K_CH + k) * 16 + g) * W_ + w) << 4) + ci] = p;
        p += g_integ[((((size_t)(n * H_ + k * HCH + (HCH - 1)) * 16 + g) * W_ + w) << 4) + ci];
    }
}

// --------------------------------------------------------------------------
// Per-ROI gather. Grid (R, 2): block = (ROI r, phase ph) covering 128
// channels each (25KB smem staging -> 8 blocks/SM).
// Thread = (local quad lq = t&31, bin-group grp = t>>5).
// Global quad cq = ph*32+lq -> group g = cq>>2, sub = cq&3; channels = 4*cq.
// --------------------------------------------------------------------------
__global__ void roipool(const int* __restrict__ rois, float* __restrict__ out,
                        int img_off, int R) {
    extern __shared__ float stage[];       // 128 * 49 floats = 25088 B
    __shared__ int sb[4 * O_];             // hs[7] he[7] ws[7] we[7]
    const int r = blockIdx.x;
    if (r >= R) return;
    const int ph  = blockIdx.y;            // 0 or 1
    const int t   = threadIdx.x;
    const int lq  = t & 31;
    const int grp = t >> 5;                // 0..7

    const int n  = rois[r * 5 + 0];
    const int x1 = rois[r * 5 + 1];
    const int y1 = rois[r * 5 + 2];
    const int x2 = rois[r * 5 + 3];
    const int y2 = rois[r * 5 + 4];

    if (t < O_) {
        const int hin = y2 - y1 + 1;
        const int win = x2 - x1 + 1;
        sb[t]          = y1 + (t * hin) / O_;                   // hs
        sb[O_ + t]     = y1 + ((t + 1) * hin + O_ - 1) / O_;    // he
        sb[2 * O_ + t] = x1 + (t * win) / O_;                   // ws
        sb[3 * O_ + t] = x1 + ((t + 1) * win + O_ - 1) / O_;    // we
    }
    __syncthreads();

    if (img_off > 0 && t == 0 && ph == 0) out[r] = (float)n;   // img_idx

    const float4 z4 = make_float4(0.f, 0.f, 0.f, 0.f);

    const int cq  = ph * 32 + lq;
    const int gg  = cq >> 2;
    const int sub = cq & 3;

    // float4 bases; per-h (or per-k) stride = 16 groups * 4W = 64W float4
    const float4* ib = (const float4*)g_integ
        + (size_t)n * ((size_t)H_ * 64 * W_) + (size_t)gg * (4 * W_) + sub;
    const float4* cb = (const float4*)g_carry
        + (size_t)n * ((size_t)K_CH * 64 * W_) + (size_t)gg * (4 * W_) + sub;

    #pragma unroll
    for (int m = 0; m < 7; ++m) {
        const int b = grp + 8 * m;
        if (b < O_ * O_) {
            const int i = b / O_;
            const int j = b - i * O_;
            const int hiT = sb[i];
            const int hiB = sb[O_ + i];
            const int wL  = sb[2 * O_ + j] - 1;   // may be -1 (pad)
            const int wR  = sb[3 * O_ + j] - 1;
            const int kB  = (hiB - 1) / HCH;
            const int kT  = (hiT > 0) ? (hiT - 1) / HCH : 0;

            // chunk-local integral corners
            float4 BR = ib[(size_t)(hiB - 1) * (64 * W_) + 4 * wR];
            float4 TR = (hiT > 0) ? ib[(size_t)(hiT - 1) * (64 * W_) + 4 * wR] : z4;
            float4 BL = (wL >= 0) ? ib[(size_t)(hiB - 1) * (64 * W_) + 4 * wL] : z4;
            float4 TL = (hiT > 0 && wL >= 0)
                      ? ib[(size_t)(hiT - 1) * (64 * W_) + 4 * wL] : z4;
            float4 s = f4sub(f4sub(BR, TR), f4sub(BL, TL));

            // carry correction; cancels when both rows in one chunk
            const bool need_carry = (hiT > 0) ? (kB != kT) : (kB != 0);
            if (need_carry) {
                float4 cR = cb[(size_t)kB * (64 * W_) + 4 * wR];
                if (hiT > 0) cR = f4sub(cR, cb[(size_t)kT * (64 * W_) + 4 * wR]);
                float4 cL = z4;
                if (wL >= 0) {
                    cL = cb[(size_t)kB * (64 * W_) + 4 * wL];
                    if (hiT > 0) cL = f4sub(cL, cb[(size_t)kT * (64 * W_) + 4 * wL]);
                }
                s = f4add(s, f4sub(cR, cL));
            }

            const float inv = 1.f / ((float)(hiB - hiT) *
                                     (float)(sb[3 * O_ + j] - sb[2 * O_ + j]));
            const int base = (4 * lq) * (O_ * O_) + b;
            stage[base]                 = s.x * inv;
            stage[base + O_ * O_]       = s.y * inv;
            stage[base + 2 * (O_ * O_)] = s.z * inv;
            stage[base + 3 * (O_ * O_)] = s.w * inv;
        }
    }
    __syncthreads();

    // coalesced float4 writeout of this half (128 ch * 49 bins)
    float4* o4 = (float4*)(out + img_off + (size_t)r * (C_ * O_ * O_)
                           + (size_t)ph * (128 * O_ * O_));
    const float4* s4 = (const float4*)stage;
    const int n4 = 128 * O_ * O_ / 4;   // 1568
    for (int p = t; p < n4; p += 256) o4[p] = s4[p];
}

// --------------------------------------------------------------------------
extern "C" void kernel_launch(void* const* d_in, const int* in_sizes, int n_in,
                              void* d_out, int out_size) {
    const float* fm   = (const float*)d_in[0];
    const int*   rois = (const int*)d_in[1];
    const int R = in_sizes[1] / 5;

    int img_off = out_size - R * C_ * O_ * O_;
    if (img_off < 0) img_off = 0;

    const int smem_bytes = 128 * O_ * O_ * (int)sizeof(float);   // 25088
    cudaFuncSetAttribute(roipool, cudaFuncAttributeMaxDynamicSharedMemorySize,
                         smem_bytes);

    dim3 gF(32, K_CH, N_);
    fused_scan<<<gF, 96>>>(fm);

    const int tot = N_ * C_ * W_;
    chunk_carry<<<(tot + 255) / 256, 256>>>();

    dim3 gR(R, 2);
    roipool<<<gR, 256, smem_bytes>>>(rois, (float*)d_out, img_off, R);
}